// round 10
// baseline (speedup 1.0000x reference)
#include <cuda_runtime.h>
#include <cuda_fp16.h>
#include <cstdint>
#include <math.h>

// ---------------------------------------------------------------------------
// Problem dims
// ---------------------------------------------------------------------------
static constexpr int E    = 16;
static constexpr int NTOK = 2048;
static constexpr int DIN  = 1024;
static constexpr int HDIM = 4096;

// GEMM tiling: CTA 128x128, BK=64 fp16 (128 B rows -> SW128 swizzle atoms)
static constexpr int BM = 128;
static constexpr int BN = 128;
static constexpr int BK = 64;
static constexpr int NSTAGE      = 4;
static constexpr int STAGE_A     = BM * BK * 2;           // 16384 B
static constexpr int STAGE_B     = BN * BK * 2;           // 16384 B
static constexpr int STAGE_BYTES = STAGE_A + STAGE_B;     // 32768 B
static constexpr int SMEM_BYTES  = NSTAGE * STAGE_BYTES;  // 131072 B

// ---------------------------------------------------------------------------
// Scratch (device globals — allocation-free contract)
// ---------------------------------------------------------------------------
__device__ __align__(128) __half g_Xh [(size_t)E * NTOK * DIN];   //  67 MB  [e][n][d]
__device__ __align__(128) __half g_W1t[(size_t)E * HDIM * DIN];   // 134 MB  [e][h][d]
__device__ __align__(128) __half g_W2t[(size_t)E * DIN  * HDIM];  // 134 MB  [e][d][h]
__device__ __align__(128) __half g_Hh [(size_t)E * NTOK * HDIM];  // 268 MB  [e][n][h]

// ---------------------------------------------------------------------------
// Helpers (base-target-safe PTX only: cp.async / ldmatrix / mma.sync)
// ---------------------------------------------------------------------------
__device__ __forceinline__ uint32_t smem_u32(const void* p) {
    uint32_t a;
    asm("{ .reg .u64 t; cvta.to.shared.u64 t, %1; cvt.u32.u64 %0, t; }" : "=r"(a) : "l"(p));
    return a;
}

__device__ __forceinline__ uint32_t swz128(uint32_t o) { return o ^ ((o >> 3) & 0x70); }

__device__ __forceinline__ void cp16(uint32_t s, const void* g) {
    asm volatile("cp.async.cg.shared.global [%0], [%1], 16;" :: "r"(s), "l"(g));
}
__device__ __forceinline__ void cp_commit() {
    asm volatile("cp.async.commit_group;" ::: "memory");
}
template <int N>
__device__ __forceinline__ void cp_wait() {
    asm volatile("cp.async.wait_group %0;" :: "n"(N) : "memory");
}

__device__ __forceinline__ void ldsm_x4(uint32_t* r, uint32_t addr) {
    asm volatile("ldmatrix.sync.aligned.m8n8.x4.shared.b16 {%0,%1,%2,%3}, [%4];"
                 : "=r"(r[0]), "=r"(r[1]), "=r"(r[2]), "=r"(r[3]) : "r"(addr));
}

__device__ __forceinline__ void mma16816(float* c, const uint32_t* a, const uint32_t* b) {
    asm volatile(
        "mma.sync.aligned.m16n8k16.row.col.f32.f16.f16.f32 "
        "{%0,%1,%2,%3}, {%4,%5,%6,%7}, {%8,%9}, {%0,%1,%2,%3};"
        : "+f"(c[0]), "+f"(c[1]), "+f"(c[2]), "+f"(c[3])
        : "r"(a[0]), "r"(a[1]), "r"(a[2]), "r"(a[3]), "r"(b[0]), "r"(b[1]));
}

__device__ __forceinline__ float gelu_erf(float x) {
    return 0.5f * x * (1.0f + erff(x * 0.70710678118654752440f));
}

// ---------------------------------------------------------------------------
// Prep: X fp32 -> fp16 (elementwise, float4 vectorized)
// ---------------------------------------------------------------------------
__global__ void convx_kernel(const float* __restrict__ x, __half* __restrict__ out, size_t n4) {
    size_t i = (size_t)blockIdx.x * blockDim.x + threadIdx.x;
    if (i >= n4) return;
    float4 v = reinterpret_cast<const float4*>(x)[i];
    __half2* o = reinterpret_cast<__half2*>(out) + 2 * i;
    o[0] = __floats2half2_rn(v.x, v.y);
    o[1] = __floats2half2_rn(v.z, v.w);
}

// ---------------------------------------------------------------------------
// Prep: transpose + convert   in[e][R][C] fp32 -> out[e][C][R] fp16
// ---------------------------------------------------------------------------
__global__ void transh_kernel(const float* __restrict__ in, __half* __restrict__ out,
                              int R, int C) {
    __shared__ float t[32][33];
    int e = blockIdx.z;
    int c0 = blockIdx.x * 32, r0 = blockIdx.y * 32;
    int tx = threadIdx.x, ty = threadIdx.y;
    const float* ip = in + ((size_t)e * R + r0) * C + c0;
#pragma unroll
    for (int u = 0; u < 4; u++)
        t[ty + 8 * u][tx] = ip[(size_t)(ty + 8 * u) * C + tx];
    __syncthreads();
    __half* op = out + ((size_t)e * C + c0) * R + r0;
#pragma unroll
    for (int u = 0; u < 4; u++)
        op[(size_t)(ty + 8 * u) * R + tx] = __float2half_rn(t[tx][ty + 8 * u]);
}

// ---------------------------------------------------------------------------
// Grouped GEMM:  D[e][BMxBN] = A[e][M][K] * B[e][N][K]^T    (both K-major fp16)
// MODE 0: epilogue erf-GELU -> fp16 store to outH (stride HDIM)
// MODE 1: epilogue fp32 store to outF (stride DIN)
// 256 threads = 8 warps (4 M x 2 N), warp tile 32x64, mma.sync m16n8k16.
// ---------------------------------------------------------------------------
template <int MODE>
__global__ void __launch_bounds__(256, 1) gemm_kernel(
    const __half* __restrict__ A, const __half* __restrict__ B,
    float* __restrict__ outF, __half* __restrict__ outH,
    int K, int BrowsPerE, int ldOut)
{
    extern __shared__ char smem[];
    const uint32_t sb = smem_u32(smem);

    const int tid  = threadIdx.x;
    const int lane = tid & 31;
    const int wid  = tid >> 5;
    const int mw   = wid >> 1;   // 0..3  (M warp)
    const int nw   = wid & 1;    // 0..1  (N warp)

    const int m0 = blockIdx.x * BM;
    const int n0 = blockIdx.y * BN;
    const int e  = blockIdx.z;
    const int S  = K >> 6;       // K / BK

    // --- producer mapping: thread -> (row, 64B half-row); 4x cp16 each for A and B
    const int prow  = tid >> 1;        // 0..127
    const int phalf = (tid & 1) * 64;  // byte offset within 128B row
    const size_t Kb = (size_t)K * 2;   // row pitch bytes
    const char* gA = (const char*)A + ((size_t)e * NTOK      + m0 + prow) * Kb + phalf;
    const char* gB = (const char*)B + ((size_t)e * BrowsPerE + n0 + prow) * Kb + phalf;
    uint32_t soA[4], soB[4];
#pragma unroll
    for (int j = 0; j < 4; j++) {
        soA[j] = swz128((uint32_t)prow * 128 + phalf + j * 16);
        soB[j] = STAGE_A + swz128((uint32_t)prow * 128 + phalf + j * 16);
    }

    auto issue = [&](int s) {
        if (s < S) {
            uint32_t sbase = sb + (s & 3) * STAGE_BYTES;
            const char* pa = gA + (size_t)s * 128;
            const char* pb = gB + (size_t)s * 128;
#pragma unroll
            for (int j = 0; j < 4; j++) {
                cp16(sbase + soA[j], pa + j * 16);
                cp16(sbase + soB[j], pb + j * 16);
            }
        }
        cp_commit();  // uniform commit keeps wait_group<2> exact at the tail
    };

    issue(0); issue(1); issue(2);

    float acc[2][8][4];
#pragma unroll
    for (int f = 0; f < 2; f++)
#pragma unroll
        for (int nf = 0; nf < 8; nf++)
#pragma unroll
            for (int q = 0; q < 4; q++) acc[f][nf][q] = 0.0f;

    // --- precomputed per-lane ldmatrix address components
    const uint32_t aRowBase = (uint32_t)(mw * 32 + (lane & 15)) * 128 + (lane & 16);
    const uint32_t bRowBase = (uint32_t)(nw * 64 + (lane & 7) + ((lane & 16) >> 1)) * 128
                            + ((lane & 8) << 1);

    for (int s = 0; s < S; s++) {
        cp_wait<2>();
        __syncthreads();
        issue(s + 3);

        const uint32_t tA = sb + (s & 3) * STAGE_BYTES;
        const uint32_t tB = tA + STAGE_A;
#pragma unroll
        for (int kk = 0; kk < 4; kk++) {
            uint32_t aF[2][4], bF[4][4];
#pragma unroll
            for (int f = 0; f < 2; f++)
                ldsm_x4(aF[f], tA + swz128(aRowBase + (uint32_t)f * 16 * 128 + kk * 32));
#pragma unroll
            for (int p = 0; p < 4; p++)
                ldsm_x4(bF[p], tB + swz128(bRowBase + (uint32_t)p * 16 * 128 + kk * 32));
#pragma unroll
            for (int f = 0; f < 2; f++)
#pragma unroll
                for (int nf = 0; nf < 8; nf++)
                    mma16816(acc[f][nf], aF[f], &bF[nf >> 1][(nf & 1) * 2]);
        }
        // next iteration's __syncthreads (before issue) protects buffer reuse
    }
    cp_wait<0>();

    // ------------------------- epilogue -------------------------
    const int g  = lane >> 2;
    const int t4 = lane & 3;
#pragma unroll
    for (int f = 0; f < 2; f++) {
        const int row = m0 + mw * 32 + f * 16 + g;
#pragma unroll
        for (int nf = 0; nf < 8; nf++) {
            const int col = n0 + nw * 64 + nf * 8 + 2 * t4;
            float* c = acc[f][nf];
            if constexpr (MODE == 0) {
                __half2 h01 = __floats2half2_rn(gelu_erf(c[0]), gelu_erf(c[1]));
                __half2 h23 = __floats2half2_rn(gelu_erf(c[2]), gelu_erf(c[3]));
                *reinterpret_cast<__half2*>(
                    outH + ((size_t)e * NTOK + row) * ldOut + col) = h01;
                *reinterpret_cast<__half2*>(
                    outH + ((size_t)e * NTOK + row + 8) * ldOut + col) = h23;
            } else {
                *reinterpret_cast<float2*>(
                    outF + ((size_t)e * NTOK + row) * ldOut + col) = make_float2(c[0], c[1]);
                *reinterpret_cast<float2*>(
                    outF + ((size_t)e * NTOK + row + 8) * ldOut + col) = make_float2(c[2], c[3]);
            }
        }
    }
}

// ---------------------------------------------------------------------------
// Host launcher
// ---------------------------------------------------------------------------
extern "C" void kernel_launch(void* const* d_in, const int* in_sizes, int n_in,
                              void* d_out, int out_size) {
    const float* x  = (const float*)d_in[0];
    const float* w1 = (const float*)d_in[1];
    const float* w2 = (const float*)d_in[2];
    float*       out = (float*)d_out;

    __half *Xh, *W1t, *W2t, *Hh;
    cudaGetSymbolAddress((void**)&Xh,  g_Xh);
    cudaGetSymbolAddress((void**)&W1t, g_W1t);
    cudaGetSymbolAddress((void**)&W2t, g_W2t);
    cudaGetSymbolAddress((void**)&Hh,  g_Hh);

    cudaFuncSetAttribute(gemm_kernel<0>, cudaFuncAttributeMaxDynamicSharedMemorySize, SMEM_BYTES);
    cudaFuncSetAttribute(gemm_kernel<1>, cudaFuncAttributeMaxDynamicSharedMemorySize, SMEM_BYTES);

    // Prep: X -> fp16 ; W1 -> [e][h][d] fp16 ; W2 -> [e][d][h] fp16
    {
        size_t n4 = (size_t)E * NTOK * DIN / 4;
        convx_kernel<<<(unsigned)((n4 + 255) / 256), 256>>>(x, Xh, n4);
    }
    dim3 tb(32, 8);
    transh_kernel<<<dim3(HDIM / 32, DIN / 32, E), tb>>>(w1, W1t, DIN, HDIM);
    transh_kernel<<<dim3(DIN / 32, HDIM / 32, E), tb>>>(w2, W2t, HDIM, DIN);

    // GEMM1: Hh = gelu(X @ W1)   [M=2048, N=4096, K=1024]
    gemm_kernel<0><<<dim3(NTOK / BM, HDIM / BN, E), 256, SMEM_BYTES>>>(
        Xh, W1t, nullptr, Hh, DIN, HDIM, HDIM);
    // GEMM2: out = Hh @ W2       [M=2048, N=1024, K=4096]
    gemm_kernel<1><<<dim3(NTOK / BM, DIN / BN, E), 256, SMEM_BYTES>>>(
        Hh, W2t, out, nullptr, HDIM, DIN, DIN);
}

// round 13
// speedup vs baseline: 1.1256x; 1.1256x over previous
#include <cuda_runtime.h>
#include <cuda_fp16.h>
#include <cstdint>
#include <math.h>

// ---------------------------------------------------------------------------
// Problem dims
// ---------------------------------------------------------------------------
static constexpr int E    = 16;
static constexpr int NTOK = 2048;
static constexpr int DIN  = 1024;
static constexpr int HDIM = 4096;

// GEMM tiling: CTA 128x128, BK=64 fp16 (128 B rows -> SW128 swizzle atoms)
static constexpr int BM = 128;
static constexpr int BN = 128;
static constexpr int BK = 64;
static constexpr int NSTAGE      = 4;
static constexpr int STAGE_A     = BM * BK * 2;           // 16384 B
static constexpr int STAGE_B     = BN * BK * 2;           // 16384 B
static constexpr int STAGE_BYTES = STAGE_A + STAGE_B;     // 32768 B
static constexpr int SMEM_BYTES  = NSTAGE * STAGE_BYTES;  // 131072 B

static constexpr int NTHREADS = 512;   // 16 warps: 4 M x 4 N, warp tile 32x32

// ---------------------------------------------------------------------------
// Scratch (device globals — allocation-free contract)
// ---------------------------------------------------------------------------
__device__ __align__(128) __half g_Xh [(size_t)E * NTOK * DIN];   //  67 MB  [e][n][d]
__device__ __align__(128) __half g_W1t[(size_t)E * HDIM * DIN];   // 134 MB  [e][h][d]
__device__ __align__(128) __half g_W2t[(size_t)E * DIN  * HDIM];  // 134 MB  [e][d][h]
__device__ __align__(128) __half g_Hh [(size_t)E * NTOK * HDIM];  // 268 MB  [e][n][h]

// ---------------------------------------------------------------------------
// Helpers (base-target-safe PTX only: cp.async / ldmatrix / mma.sync)
// ---------------------------------------------------------------------------
__device__ __forceinline__ uint32_t smem_u32(const void* p) {
    uint32_t a;
    asm("{ .reg .u64 t; cvta.to.shared.u64 t, %1; cvt.u32.u64 %0, t; }" : "=r"(a) : "l"(p));
    return a;
}

__device__ __forceinline__ uint32_t swz128(uint32_t o) { return o ^ ((o >> 3) & 0x70); }

__device__ __forceinline__ void cp16(uint32_t s, const void* g) {
    asm volatile("cp.async.cg.shared.global [%0], [%1], 16;" :: "r"(s), "l"(g));
}
__device__ __forceinline__ void cp_commit() {
    asm volatile("cp.async.commit_group;" ::: "memory");
}
template <int N>
__device__ __forceinline__ void cp_wait() {
    asm volatile("cp.async.wait_group %0;" :: "n"(N) : "memory");
}

__device__ __forceinline__ void ldsm_x4(uint32_t* r, uint32_t addr) {
    asm volatile("ldmatrix.sync.aligned.m8n8.x4.shared.b16 {%0,%1,%2,%3}, [%4];"
                 : "=r"(r[0]), "=r"(r[1]), "=r"(r[2]), "=r"(r[3]) : "r"(addr));
}

__device__ __forceinline__ void mma16816(float* c, const uint32_t* a, const uint32_t* b) {
    asm volatile(
        "mma.sync.aligned.m16n8k16.row.col.f32.f16.f16.f32 "
        "{%0,%1,%2,%3}, {%4,%5,%6,%7}, {%8,%9}, {%0,%1,%2,%3};"
        : "+f"(c[0]), "+f"(c[1]), "+f"(c[2]), "+f"(c[3])
        : "r"(a[0]), "r"(a[1]), "r"(a[2]), "r"(a[3]), "r"(b[0]), "r"(b[1]));
}

__device__ __forceinline__ float gelu_erf(float x) {
    return 0.5f * x * (1.0f + erff(x * 0.70710678118654752440f));
}

// ---------------------------------------------------------------------------
// Prep: X fp32 -> fp16 (elementwise, float4 vectorized)
// ---------------------------------------------------------------------------
__global__ void convx_kernel(const float* __restrict__ x, __half* __restrict__ out, size_t n4) {
    size_t i = (size_t)blockIdx.x * blockDim.x + threadIdx.x;
    if (i >= n4) return;
    float4 v = reinterpret_cast<const float4*>(x)[i];
    __half2* o = reinterpret_cast<__half2*>(out) + 2 * i;
    o[0] = __floats2half2_rn(v.x, v.y);
    o[1] = __floats2half2_rn(v.z, v.w);
}

// ---------------------------------------------------------------------------
// Prep: transpose + convert   in[e][R][C] fp32 -> out[e][C][R] fp16
// ---------------------------------------------------------------------------
__global__ void transh_kernel(const float* __restrict__ in, __half* __restrict__ out,
                              int R, int C) {
    __shared__ float t[32][33];
    int e = blockIdx.z;
    int c0 = blockIdx.x * 32, r0 = blockIdx.y * 32;
    int tx = threadIdx.x, ty = threadIdx.y;
    const float* ip = in + ((size_t)e * R + r0) * C + c0;
#pragma unroll
    for (int u = 0; u < 4; u++)
        t[ty + 8 * u][tx] = ip[(size_t)(ty + 8 * u) * C + tx];
    __syncthreads();
    __half* op = out + ((size_t)e * C + c0) * R + r0;
#pragma unroll
    for (int u = 0; u < 4; u++)
        op[(size_t)(ty + 8 * u) * R + tx] = __float2half_rn(t[tx][ty + 8 * u]);
}

// ---------------------------------------------------------------------------
// Grouped GEMM:  D[e][BMxBN] = A[e][M][K] * B[e][N][K]^T    (both K-major fp16)
// MODE 0: epilogue erf-GELU -> fp16 store to outH (stride HDIM)
// MODE 1: epilogue fp32 store to outF (stride DIN)
// 512 threads = 16 warps (4 M x 4 N), warp tile 32x32, mma.sync m16n8k16.
// ---------------------------------------------------------------------------
template <int MODE>
__global__ void __launch_bounds__(NTHREADS, 1) gemm_kernel(
    const __half* __restrict__ A, const __half* __restrict__ B,
    float* __restrict__ outF, __half* __restrict__ outH,
    int K, int BrowsPerE, int ldOut)
{
    extern __shared__ char smem[];
    const uint32_t sb = smem_u32(smem);

    const int tid  = threadIdx.x;
    const int lane = tid & 31;
    const int wid  = tid >> 5;
    const int mw   = wid >> 2;   // 0..3  (M warp)
    const int nw   = wid & 3;    // 0..3  (N warp)

    const int m0 = blockIdx.x * BM;
    const int n0 = blockIdx.y * BN;
    const int e  = blockIdx.z;
    const int S  = K >> 6;       // K / BK

    // --- producer mapping: thread -> (row, 32B quadrant); 2x cp16 each for A and B
    const int prow  = tid >> 2;        // 0..127
    const int pquad = (tid & 3) * 32;  // byte offset within 128B row
    const size_t Kb = (size_t)K * 2;   // row pitch bytes
    const char* gA = (const char*)A + ((size_t)e * NTOK      + m0 + prow) * Kb + pquad;
    const char* gB = (const char*)B + ((size_t)e * BrowsPerE + n0 + prow) * Kb + pquad;
    uint32_t soA[2], soB[2];
#pragma unroll
    for (int j = 0; j < 2; j++) {
        soA[j] = swz128((uint32_t)prow * 128 + pquad + j * 16);
        soB[j] = STAGE_A + swz128((uint32_t)prow * 128 + pquad + j * 16);
    }

    auto issue = [&](int s) {
        if (s < S) {
            uint32_t sbase = sb + (s & 3) * STAGE_BYTES;
            const char* pa = gA + (size_t)s * 128;
            const char* pb = gB + (size_t)s * 128;
#pragma unroll
            for (int j = 0; j < 2; j++) {
                cp16(sbase + soA[j], pa + j * 16);
                cp16(sbase + soB[j], pb + j * 16);
            }
        }
        cp_commit();  // uniform commit keeps wait_group<2> exact at the tail
    };

    issue(0); issue(1); issue(2);

    float acc[2][4][4];
#pragma unroll
    for (int f = 0; f < 2; f++)
#pragma unroll
        for (int nf = 0; nf < 4; nf++)
#pragma unroll
            for (int q = 0; q < 4; q++) acc[f][nf][q] = 0.0f;

    // --- precomputed per-lane ldmatrix address components
    const uint32_t aRowBase = (uint32_t)(mw * 32 + (lane & 15)) * 128 + (lane & 16);
    const uint32_t bRowBase = (uint32_t)(nw * 32 + (lane & 7) + ((lane & 16) >> 1)) * 128
                            + ((lane & 8) << 1);

    for (int s = 0; s < S; s++) {
        cp_wait<2>();
        __syncthreads();
        issue(s + 3);

        const uint32_t tA = sb + (s & 3) * STAGE_BYTES;
        const uint32_t tB = tA + STAGE_A;
#pragma unroll
        for (int kk = 0; kk < 4; kk++) {
            uint32_t aF[2][4], bF[2][4];
#pragma unroll
            for (int f = 0; f < 2; f++)
                ldsm_x4(aF[f], tA + swz128(aRowBase + (uint32_t)f * 16 * 128 + kk * 32));
#pragma unroll
            for (int p = 0; p < 2; p++)
                ldsm_x4(bF[p], tB + swz128(bRowBase + (uint32_t)p * 16 * 128 + kk * 32));
#pragma unroll
            for (int f = 0; f < 2; f++)
#pragma unroll
                for (int nf = 0; nf < 4; nf++)
                    mma16816(acc[f][nf], aF[f], &bF[nf >> 1][(nf & 1) * 2]);
        }
        // next iteration's __syncthreads (before issue) protects buffer reuse
    }
    cp_wait<0>();

    // ------------------------- epilogue -------------------------
    const int g  = lane >> 2;
    const int t4 = lane & 3;
#pragma unroll
    for (int f = 0; f < 2; f++) {
        const int row = m0 + mw * 32 + f * 16 + g;
#pragma unroll
        for (int nf = 0; nf < 4; nf++) {
            const int col = n0 + nw * 32 + nf * 8 + 2 * t4;
            float* c = acc[f][nf];
            if constexpr (MODE == 0) {
                __half2 h01 = __floats2half2_rn(gelu_erf(c[0]), gelu_erf(c[1]));
                __half2 h23 = __floats2half2_rn(gelu_erf(c[2]), gelu_erf(c[3]));
                *reinterpret_cast<__half2*>(
                    outH + ((size_t)e * NTOK + row) * ldOut + col) = h01;
                *reinterpret_cast<__half2*>(
                    outH + ((size_t)e * NTOK + row + 8) * ldOut + col) = h23;
            } else {
                *reinterpret_cast<float2*>(
                    outF + ((size_t)e * NTOK + row) * ldOut + col) = make_float2(c[0], c[1]);
                *reinterpret_cast<float2*>(
                    outF + ((size_t)e * NTOK + row + 8) * ldOut + col) = make_float2(c[2], c[3]);
            }
        }
    }
}

// ---------------------------------------------------------------------------
// Host launcher
// ---------------------------------------------------------------------------
extern "C" void kernel_launch(void* const* d_in, const int* in_sizes, int n_in,
                              void* d_out, int out_size) {
    const float* x  = (const float*)d_in[0];
    const float* w1 = (const float*)d_in[1];
    const float* w2 = (const float*)d_in[2];
    float*       out = (float*)d_out;

    __half *Xh, *W1t, *W2t, *Hh;
    cudaGetSymbolAddress((void**)&Xh,  g_Xh);
    cudaGetSymbolAddress((void**)&W1t, g_W1t);
    cudaGetSymbolAddress((void**)&W2t, g_W2t);
    cudaGetSymbolAddress((void**)&Hh,  g_Hh);

    cudaFuncSetAttribute(gemm_kernel<0>, cudaFuncAttributeMaxDynamicSharedMemorySize, SMEM_BYTES);
    cudaFuncSetAttribute(gemm_kernel<1>, cudaFuncAttributeMaxDynamicSharedMemorySize, SMEM_BYTES);

    // Prep: X -> fp16 ; W1 -> [e][h][d] fp16 ; W2 -> [e][d][h] fp16
    {
        size_t n4 = (size_t)E * NTOK * DIN / 4;
        convx_kernel<<<(unsigned)((n4 + 255) / 256), 256>>>(x, Xh, n4);
    }
    dim3 tb(32, 8);
    transh_kernel<<<dim3(HDIM / 32, DIN / 32, E), tb>>>(w1, W1t, DIN, HDIM);
    transh_kernel<<<dim3(DIN / 32, HDIM / 32, E), tb>>>(w2, W2t, HDIM, DIN);

    // GEMM1: Hh = gelu(X @ W1)   [M=2048, N=4096, K=1024]
    gemm_kernel<0><<<dim3(NTOK / BM, HDIM / BN, E), NTHREADS, SMEM_BYTES>>>(
        Xh, W1t, nullptr, Hh, DIN, HDIM, HDIM);
    // GEMM2: out = Hh @ W2       [M=2048, N=1024, K=4096]
    gemm_kernel<1><<<dim3(NTOK / BM, DIN / BN, E), NTHREADS, SMEM_BYTES>>>(
        Hh, W2t, out, nullptr, HDIM, DIN, DIN);
}